// round 9
// baseline (speedup 1.0000x reference)
#include <cuda_runtime.h>
#include <cuda_bf16.h>

// ---------------------------------------------------------------------------
// PatchTokenizer: entropy-masked multi-scale patch gather.
// Output layout (float32, tuple order, concatenated):
//   sel16 | full32 | sel32 | flat16 | flat32 | output_mask | seqlens |
//   cu_seqlens | max_seqlen | retained_frac
// ---------------------------------------------------------------------------

#define NCOARSE 8192    // 32 * 16 * 16
#define NFINE   32768   // 32 * 32 * 32

__device__ int d_m32[NCOARSE];        // coarse keep mask (entropy < 7.2)
__device__ int d_idx32[NCOARSE + 1];  // exclusive prefix of m32 (+ sentinel N32)
__device__ int d_off[6];              // {full32_f4, sel32_f4, OFF_f16, OFF_f32, OFF_mask, sumseq}
__device__ int d_cu[33];              // per-batch cu_seqlens (int)
__device__ int d_n32b[32];            // per-batch coarse kept count
__device__ int d_done;                // last-block-done counter (self-resetting)

// ---------------- block-wide exclusive scan (any blockDim mult of 32) ------
__device__ __forceinline__ int block_excl_scan(int v, int& tot)
{
    __shared__ int ws[32];
    __shared__ int stot;
    const int lane = threadIdx.x & 31, wid = threadIdx.x >> 5;
    const int nw = blockDim.x >> 5;
    int x = v;
    #pragma unroll
    for (int d = 1; d < 32; d <<= 1) {
        int y = __shfl_up_sync(0xffffffffu, x, d);
        if (lane >= d) x += y;
    }
    if (lane == 31) ws[wid] = x;
    __syncthreads();
    if (wid == 0) {
        int w = (lane < nw) ? ws[lane] : 0;
        int xx = w;
        #pragma unroll
        for (int d = 1; d < 32; d <<= 1) {
            int y = __shfl_up_sync(0xffffffffu, xx, d);
            if (lane >= d) xx += y;
        }
        ws[lane] = xx - w;              // exclusive warp-prefix
        if (lane == 31) stot = xx;
    }
    __syncthreads();
    tot = stot;
    int rr = ws[wid] + x - v;
    __syncthreads();
    return rr;
}

// ---------------- Kernel 1: entropy + fused scan (last block) --------------
// Entropy: R6-proven 256-thread / 512-bin shared histogram.
// The last block to finish performs the coarse prefix scan + scalar outputs
// inline (overlaps the drain of the other entropy blocks; kills one launch).
__global__ void __launch_bounds__(256) entropy_scan_kernel(
    const float* __restrict__ img, const float* __restrict__ mean,
    const float* __restrict__ stdv, float* __restrict__ out)
{
    __shared__ int hist[512];
    const int p = blockIdx.x;          // coarse patch id
    const int t = threadIdx.x;         // 256 threads
    hist[t] = 0; hist[t + 256] = 0;
    __syncthreads();

    const int b  = p >> 8;
    const int ic = (p >> 4) & 15;
    const int jc = p & 15;
    const float s0 = stdv[0] * 255.0f, s1 = stdv[1] * 255.0f, s2 = stdv[2] * 255.0f;
    const float m0 = mean[0] * 255.0f, m1 = mean[1] * 255.0f, m2 = mean[2] * 255.0f;
    const float4* base4 = (const float4*)(img + (size_t)b * 786432);

    const int r  = t >> 3;
    const int f4 = t & 7;
    const int a  = (ic * 32 + r) * 128 + jc * 8 + f4;
    float4 v0 = base4[a];
    float4 v1 = base4[65536 + a];
    float4 v2 = base4[131072 + a];

    #pragma unroll
    for (int i = 0; i < 4; i++) {
        float u0 = fminf(fmaxf(fmaf((&v0.x)[i], s0, m0), 0.0f), 255.0f);
        float u1 = fminf(fmaxf(fmaf((&v1.x)[i], s1, m1), 0.0f), 255.0f);
        float u2 = fminf(fmaxf(fmaf((&v2.x)[i], s2, m2), 0.0f), 255.0f);
        float gray = fmaf(u0, 0.2989f, fmaf(u1, 0.587f, u2 * 0.114f));
        int bin = (int)(gray * 2.0f);      // gray in [0, 254.98] -> bin in [0, 509]
        atomicAdd(&hist[bin], 1);
    }
    __syncthreads();

    float e = 0.0f;
    #pragma unroll
    for (int i = 0; i < 2; i++) {
        int c = hist[t + i * 256];
        if (c) {
            float pr = (float)c * (1.0f / 1024.0f);
            e -= pr * __log2f(pr + 1e-10f);   // single MUFU.LG2
        }
    }
    #pragma unroll
    for (int d = 16; d > 0; d >>= 1) e += __shfl_down_sync(0xffffffffu, e, d);
    __shared__ float we[8];
    int lane = t & 31, wid = t >> 5;
    if (lane == 0) we[wid] = e;
    __syncthreads();
    if (t == 0) {
        float s = 0.0f;
        #pragma unroll
        for (int i = 0; i < 8; i++) s += we[i];
        d_m32[p] = (s < 7.2f) ? 1 : 0;
    }

    // ---- last-block election -------------------------------------------------
    __shared__ int isLast;
    if (t == 0) {
        __threadfence();                           // publish d_m32[p]
        isLast = (atomicAdd(&d_done, 1) == NCOARSE - 1);
    }
    __syncthreads();
    if (!isLast) return;
    if (t == 0) d_done = 0;                        // reset for graph replay
    __threadfence();                               // see all d_m32 writes

    // ---- fused scan: 256 threads x 32 elems --------------------------------
    __shared__ int sh_n32[32];
    __shared__ int sh_cu[33];

    const int base = t * 32;
    int csum = 0;
    #pragma unroll 8
    for (int i = 0; i < 32; i++) csum += d_m32[base + i];
    int tot32;
    int cex = block_excl_scan(csum, tot32);
    {
        int ee = cex;
        #pragma unroll 8
        for (int i = 0; i < 32; i++) {
            int v = d_m32[base + i];
            d_idx32[base + i] = ee;
            ee += v;
        }
    }
    __syncthreads();

    const int N32 = tot32;
    const int N16 = NFINE - 4 * N32;

    if (t < 32) {
        int start = d_idx32[t * 256];
        int end   = (t == 31) ? N32 : d_idx32[(t + 1) * 256];
        sh_n32[t] = end - start;
    }
    __syncthreads();
    if (t == 0) {
        int acc = 0; sh_cu[0] = 0;
        for (int bb = 0; bb < 32; bb++) { acc += 1025 - 3 * sh_n32[bb]; sh_cu[bb + 1] = acc; }
    }
    __syncthreads();

    const int sumseq   = sh_cu[32];           // = 32 + N16 + N32
    const int OFF1     = N16 * 768;
    const int OFF2     = OFF1 + N32 * 3072;
    const int OFF_f16  = OFF2 + N32 * 768;
    const int OFF_f32  = OFF_f16 + NFINE;
    const int OFF_mask = OFF_f32 + NCOARSE;
    const int OFF_seq  = OFF_mask + sumseq;
    const int OFF_cu   = OFF_seq + 32;
    const int OFF_max  = OFF_cu + 33;
    const int OFF_frac = OFF_max + 1;

    if (t < 32) {
        d_n32b[t] = sh_n32[t];
        d_cu[t]   = sh_cu[t];
        out[OFF_seq + t] = (float)(1025 - 3 * sh_n32[t]);
        out[OFF_cu + t]  = (float)sh_cu[t];
    }
    if (t == 0) {
        d_idx32[NCOARSE] = N32;               // sentinel for row-end lookups
        d_cu[32] = sh_cu[32];
        d_off[0] = N16 * 192;                 // full32 start, float4 units
        d_off[1] = N16 * 192 + N32 * 768;     // sel32 start, float4 units
        d_off[2] = OFF_f16;
        d_off[3] = OFF_f32;
        d_off[4] = OFF_mask;
        d_off[5] = sumseq;
        out[OFF_cu + 32] = (float)sh_cu[32];
        int mx = 0;
        for (int bb = 0; bb < 32; bb++) mx = max(mx, 1025 - 3 * sh_n32[bb]);
        out[OFF_max]  = (float)mx;
        out[OFF_frac] = (float)sumseq / 32768.0f;
    }
}

// ---------------- Kernel 2: gathers (reverse order) + dense fills ----------
// 192 threads/block, 4 coarse patches per block, grid 2048, REVERSE p order
// so gather reads the most-recently-cached image lines first (L2 LRU).
__global__ void __launch_bounds__(192) gather_kernel(
    const float* __restrict__ img, float* __restrict__ out)
{
    const int B  = blockIdx.x;         // 2048 blocks
    const int t  = threadIdx.x;        // 192 threads
    const int p0 = (2047 - B) * 4;     // reverse order
    const int b  = p0 >> 8;
    const float4* base4 = (const float4*)(img + (size_t)b * 786432);
    float4* out4 = (float4*)out;

    const int c  = t >> 6;             // channel 0..2
    const int w0 = t & 63;
    const int r  = w0 >> 2, s4 = w0 & 3;

    const int off0 = d_off[0];
    const int off1 = d_off[1];

    // stage masks + coarse prefixes; derive fine slots analytically
    __shared__ int sm[4], sslot[4], srow[2];   // srow = {idx32[prs], idx32[prs+16]}
    if (t < 4) { sm[t] = d_m32[p0 + t]; sslot[t] = d_idx32[p0 + t]; }
    if (t == 8)  srow[0] = d_idx32[p0 & ~15];
    if (t == 9)  srow[1] = d_idx32[(p0 & ~15) + 16];
    __syncthreads();

    const int prs    = p0 & ~15;
    const int Urs    = prs - srow[0];               // unkept coarse before row
    const int Urowt  = (prs + 16 - srow[1]) - Urs;  // unkept in whole row

    #pragma unroll
    for (int kp = 0; kp < 4; kp++) {
        const int p  = p0 + kp;
        const int ic = (p >> 4) & 15;
        const int jc = p & 15;
        float4 v[4];
        #pragma unroll
        for (int k = 0; k < 4; k++) {
            int di = k >> 1, dj = k & 1;
            int y  = ic * 32 + di * 16 + r;
            int xs = jc * 8 + dj * 4 + s4;
            v[k] = base4[c * 65536 + y * 128 + xs];
        }
        if (!sm[kp]) {
            const int u    = 1;                     // this patch unkept
            const int Urow = (p - sslot[kp]) - Urs; // unkept before p in row
            int dst16[4];
            dst16[0] = 4 * Urs + 2 * Urow;              // (di=0,dj=0)
            dst16[1] = dst16[0] + u;                    // (0,1)
            dst16[2] = 4 * Urs + 2 * Urowt + 2 * Urow;  // (1,0)
            dst16[3] = dst16[2] + u;                    // (1,1)
            #pragma unroll
            for (int k = 0; k < 4; k++)
                __stcs(&out4[(size_t)dst16[k] * 192 + c * 64 + w0], v[k]);
        } else {
            const size_t o1 = (size_t)off0 + (size_t)sslot[kp] * 768;
            #pragma unroll
            for (int k = 0; k < 4; k++)
                __stcs(&out4[o1 + k * 192 + c * 64 + w0], v[k]);
            // sel32: 2x2-mean downsample (source lines L1-hot from v[] loads)
            {
                int y0 = ic * 32 + 2 * r;
                int xb = jc * 8 + 2 * s4;
                float4 a0 = base4[c * 65536 + y0 * 128 + xb];
                float4 a1 = base4[c * 65536 + y0 * 128 + xb + 1];
                float4 b0 = base4[c * 65536 + (y0 + 1) * 128 + xb];
                float4 b1 = base4[c * 65536 + (y0 + 1) * 128 + xb + 1];
                float4 o;
                o.x = 0.25f * (a0.x + a0.y + b0.x + b0.y);
                o.y = 0.25f * (a0.z + a0.w + b0.z + b0.w);
                o.z = 0.25f * (a1.x + a1.y + b1.x + b1.y);
                o.w = 0.25f * (a1.z + a1.w + b1.z + b1.w);
                __stcs(&out4[(size_t)off1 + (size_t)sslot[kp] * 192 + t], o);
            }
        }
    }

    // ---- dense fills: flat16 | flat32 | output_mask -----------------------
    {
        const int gi = B * 192 + t;
        const int T  = 40960 + d_off[5];       // 32768 + 8192 + sumseq
        if (gi < T) {
            if (gi < 32768) {
                int q = gi;
                int m = d_m32[(q >> 10) * 256 + (((q >> 5) & 31) >> 1) * 16 + ((q & 31) >> 1)];
                out[d_off[2] + q] = (float)(1 - m);
            } else if (gi < 40960) {
                int p = gi - 32768;
                out[d_off[3] + p] = (float)d_m32[p];
            } else {
                int j = gi - 40960;            // index into output_mask
                int lo = 0, hi = 32;
                while (hi - lo > 1) {
                    int mid = (lo + hi) >> 1;
                    if (j >= d_cu[mid]) lo = mid; else hi = mid;
                }
                int rel  = j - d_cu[lo];
                int n16b = 1024 - 4 * d_n32b[lo];
                float val = (rel == 0) ? -1.0f : (rel - 1 < n16b ? 1.0f : 2.0f);
                out[d_off[4] + j] = val;
            }
        }
    }
}

// ---------------------------------------------------------------------------
extern "C" void kernel_launch(void* const* d_in, const int* in_sizes, int n_in,
                              void* d_out, int out_size)
{
    const float* img  = (const float*)d_in[0];
    const float* mean = (const float*)d_in[1];
    const float* stdv = (const float*)d_in[2];
    float* out = (float*)d_out;

    entropy_scan_kernel<<<NCOARSE, 256>>>(img, mean, stdv, out);
    gather_kernel<<<2048, 192>>>(img, out);
}

// round 10
// speedup vs baseline: 1.2143x; 1.2143x over previous
#include <cuda_runtime.h>
#include <cuda_bf16.h>

// ---------------------------------------------------------------------------
// PatchTokenizer: entropy-masked multi-scale patch gather.
// Output layout (float32, tuple order, concatenated):
//   sel16 | full32 | sel32 | flat16 | flat32 | output_mask | seqlens |
//   cu_seqlens | max_seqlen | retained_frac
// ---------------------------------------------------------------------------

#define NCOARSE 8192    // 32 * 16 * 16
#define NFINE   32768   // 32 * 32 * 32

__device__ int d_m32[NCOARSE];        // coarse keep mask (entropy < 7.2)
__device__ int d_idx32[NCOARSE + 1];  // exclusive prefix of m32 (+ sentinel N32)
__device__ int d_off[6];              // {full32_f4, sel32_f4, OFF_f16, OFF_f32, OFF_mask, sumseq}
__device__ int d_cu[33];              // per-batch cu_seqlens (int)
__device__ int d_n32b[32];            // per-batch coarse kept count

// ---------------- Kernel 1: per-coarse-patch histogram entropy -------------
// (R6-proven: 256 threads, single 512-bin shared histogram)
__global__ void __launch_bounds__(256) entropy_kernel(
    const float* __restrict__ img, const float* __restrict__ mean,
    const float* __restrict__ stdv)
{
    __shared__ int hist[512];
    const int p = blockIdx.x;          // coarse patch id
    const int t = threadIdx.x;         // 256 threads
    hist[t] = 0; hist[t + 256] = 0;
    __syncthreads();

    const int b  = p >> 8;
    const int ic = (p >> 4) & 15;
    const int jc = p & 15;
    const float s0 = stdv[0] * 255.0f, s1 = stdv[1] * 255.0f, s2 = stdv[2] * 255.0f;
    const float m0 = mean[0] * 255.0f, m1 = mean[1] * 255.0f, m2 = mean[2] * 255.0f;
    const float4* base4 = (const float4*)(img + (size_t)b * 786432);

    const int r  = t >> 3;
    const int f4 = t & 7;
    const int a  = (ic * 32 + r) * 128 + jc * 8 + f4;
    float4 v0 = base4[a];
    float4 v1 = base4[65536 + a];
    float4 v2 = base4[131072 + a];

    #pragma unroll
    for (int i = 0; i < 4; i++) {
        float u0 = fminf(fmaxf(fmaf((&v0.x)[i], s0, m0), 0.0f), 255.0f);
        float u1 = fminf(fmaxf(fmaf((&v1.x)[i], s1, m1), 0.0f), 255.0f);
        float u2 = fminf(fmaxf(fmaf((&v2.x)[i], s2, m2), 0.0f), 255.0f);
        float gray = fmaf(u0, 0.2989f, fmaf(u1, 0.587f, u2 * 0.114f));
        int bin = (int)(gray * 2.0f);      // gray in [0, 254.98] -> bin in [0, 509]
        atomicAdd(&hist[bin], 1);
    }
    __syncthreads();

    float e = 0.0f;
    #pragma unroll
    for (int i = 0; i < 2; i++) {
        int c = hist[t + i * 256];
        if (c) {
            float pr = (float)c * (1.0f / 1024.0f);
            e -= pr * __log2f(pr + 1e-10f);   // single MUFU.LG2
        }
    }
    #pragma unroll
    for (int d = 16; d > 0; d >>= 1) e += __shfl_down_sync(0xffffffffu, e, d);
    __shared__ float we[8];
    int lane = t & 31, wid = t >> 5;
    if (lane == 0) we[wid] = e;
    __syncthreads();
    if (t == 0) {
        float s = 0.0f;
        #pragma unroll
        for (int i = 0; i < 8; i++) s += we[i];
        d_m32[p] = (s < 7.2f) ? 1 : 0;
    }
}

// ---------------- block-wide exclusive scan (blockDim = 1024) --------------
__device__ __forceinline__ int block_excl_scan(int v, int& tot)
{
    __shared__ int ws[32];
    __shared__ int stot;
    const int lane = threadIdx.x & 31, wid = threadIdx.x >> 5;
    int x = v;
    #pragma unroll
    for (int d = 1; d < 32; d <<= 1) {
        int y = __shfl_up_sync(0xffffffffu, x, d);
        if (lane >= d) x += y;
    }
    if (lane == 31) ws[wid] = x;
    __syncthreads();
    if (wid == 0) {
        int w = ws[lane];
        int xx = w;
        #pragma unroll
        for (int d = 1; d < 32; d <<= 1) {
            int y = __shfl_up_sync(0xffffffffu, xx, d);
            if (lane >= d) xx += y;
        }
        ws[lane] = xx - w;              // exclusive warp-prefix
        if (lane == 31) stot = xx;
    }
    __syncthreads();
    tot = stot;
    int rr = ws[wid] + x - v;
    __syncthreads();
    return rr;
}

// ---------------- Kernel 2: coarse prefix sum + scalar outputs -------------
__global__ void __launch_bounds__(1024) scan_kernel(float* __restrict__ out)
{
    const int t = threadIdx.x;          // 1024 threads, 1 block
    __shared__ int sh_n32[32];
    __shared__ int sh_cu[33];

    // coarse scan: 8 elems/thread
    int cv[8]; int csum = 0;
    #pragma unroll
    for (int i = 0; i < 8; i++) { cv[i] = d_m32[t * 8 + i]; csum += cv[i]; }
    int tot32;
    int cex = block_excl_scan(csum, tot32);
    {
        int e = cex;
        #pragma unroll
        for (int i = 0; i < 8; i++) { d_idx32[t * 8 + i] = e; e += cv[i]; }
    }
    __syncthreads();

    const int N32 = tot32;
    const int N16 = NFINE - 4 * N32;

    if (t < 32) {
        int start = d_idx32[t * 256];
        int end   = (t == 31) ? N32 : d_idx32[(t + 1) * 256];
        sh_n32[t] = end - start;
    }
    __syncthreads();
    if (t == 0) {
        int acc = 0; sh_cu[0] = 0;
        for (int b = 0; b < 32; b++) { acc += 1025 - 3 * sh_n32[b]; sh_cu[b + 1] = acc; }
    }
    __syncthreads();

    const int sumseq   = sh_cu[32];           // = 32 + N16 + N32
    const int OFF1     = N16 * 768;
    const int OFF2     = OFF1 + N32 * 3072;
    const int OFF_f16  = OFF2 + N32 * 768;
    const int OFF_f32  = OFF_f16 + NFINE;
    const int OFF_mask = OFF_f32 + NCOARSE;
    const int OFF_seq  = OFF_mask + sumseq;
    const int OFF_cu   = OFF_seq + 32;
    const int OFF_max  = OFF_cu + 33;
    const int OFF_frac = OFF_max + 1;

    if (t < 32) {
        d_n32b[t] = sh_n32[t];
        d_cu[t]   = sh_cu[t];
        out[OFF_seq + t] = (float)(1025 - 3 * sh_n32[t]);
        out[OFF_cu + t]  = (float)sh_cu[t];
    }
    if (t == 0) {
        d_idx32[NCOARSE] = N32;               // sentinel for row-end lookups
        d_cu[32] = sh_cu[32];
        d_off[0] = N16 * 192;                 // full32 start, float4 units
        d_off[1] = N16 * 192 + N32 * 768;     // sel32 start, float4 units
        d_off[2] = OFF_f16;
        d_off[3] = OFF_f32;
        d_off[4] = OFF_mask;
        d_off[5] = sumseq;
        out[OFF_cu + 32] = (float)sh_cu[32];
        int mx = 0;
        for (int b = 0; b < 32; b++) mx = max(mx, 1025 - 3 * sh_n32[b]);
        out[OFF_max]  = (float)mx;
        out[OFF_frac] = (float)sumseq / 32768.0f;
    }
}

// ---------------- Kernel 3: gathers (reverse order) + dense fills ----------
// 384 threads/block (two 192-thread halves), 8 coarse patches per block,
// grid 1024: 12 warps/block packs ~60/64 warps/SM (vs 46.8% at 192thr).
__global__ void __launch_bounds__(384) gather_kernel(
    const float* __restrict__ img, float* __restrict__ out)
{
    const int B  = blockIdx.x;         // 1024 blocks
    const int t  = threadIdx.x;        // 384 threads
    const int p0 = (1023 - B) * 8;     // reverse order; 8 patches, same row
    const int b  = p0 >> 8;            // 32 blocks per batch
    const float4* base4 = (const float4*)(img + (size_t)b * 786432);
    float4* out4 = (float4*)out;

    const int h  = t >= 192;           // half: patches 4h..4h+3
    const int tl = t - h * 192;        // local thread 0..191
    const int c  = tl >> 6;            // channel 0..2
    const int w0 = tl & 63;
    const int r  = w0 >> 2, s4 = w0 & 3;

    const int off0 = d_off[0];
    const int off1 = d_off[1];

    // stage masks + coarse prefixes; derive fine slots analytically
    __shared__ int sm[8], sslot[8], srow[2];   // srow = {idx32[prs], idx32[prs+16]}
    if (t < 8) { sm[t] = d_m32[p0 + t]; sslot[t] = d_idx32[p0 + t]; }
    if (t == 16) srow[0] = d_idx32[p0 & ~15];
    if (t == 17) srow[1] = d_idx32[(p0 & ~15) + 16];
    __syncthreads();

    const int prs    = p0 & ~15;
    const int Urs    = prs - srow[0];               // unkept coarse before row
    const int Urowt  = (prs + 16 - srow[1]) - Urs;  // unkept in whole row

    #pragma unroll
    for (int kq = 0; kq < 4; kq++) {
        const int kp = h * 4 + kq;
        const int p  = p0 + kp;
        const int ic = (p >> 4) & 15;
        const int jc = p & 15;
        float4 v[4];
        #pragma unroll
        for (int k = 0; k < 4; k++) {
            int di = k >> 1, dj = k & 1;
            int y  = ic * 32 + di * 16 + r;
            int xs = jc * 8 + dj * 4 + s4;
            v[k] = base4[c * 65536 + y * 128 + xs];
        }
        if (!sm[kp]) {
            const int u    = 1;                     // this patch unkept
            const int Urow = (p - sslot[kp]) - Urs; // unkept before p in row
            int dst16[4];
            dst16[0] = 4 * Urs + 2 * Urow;              // (di=0,dj=0)
            dst16[1] = dst16[0] + u;                    // (0,1)
            dst16[2] = 4 * Urs + 2 * Urowt + 2 * Urow;  // (1,0)
            dst16[3] = dst16[2] + u;                    // (1,1)
            #pragma unroll
            for (int k = 0; k < 4; k++)
                __stcs(&out4[(size_t)dst16[k] * 192 + c * 64 + w0], v[k]);
        } else {
            const size_t o1 = (size_t)off0 + (size_t)sslot[kp] * 768;
            #pragma unroll
            for (int k = 0; k < 4; k++)
                __stcs(&out4[o1 + k * 192 + c * 64 + w0], v[k]);
            // sel32: 2x2-mean downsample (source lines L1-hot from v[] loads)
            {
                int y0 = ic * 32 + 2 * r;
                int xb = jc * 8 + 2 * s4;
                float4 a0 = base4[c * 65536 + y0 * 128 + xb];
                float4 a1 = base4[c * 65536 + y0 * 128 + xb + 1];
                float4 b0 = base4[c * 65536 + (y0 + 1) * 128 + xb];
                float4 b1 = base4[c * 65536 + (y0 + 1) * 128 + xb + 1];
                float4 o;
                o.x = 0.25f * (a0.x + a0.y + b0.x + b0.y);
                o.y = 0.25f * (a0.z + a0.w + b0.z + b0.w);
                o.z = 0.25f * (a1.x + a1.y + b1.x + b1.y);
                o.w = 0.25f * (a1.z + a1.w + b1.z + b1.w);
                __stcs(&out4[(size_t)off1 + (size_t)sslot[kp] * 192 + tl], o);
            }
        }
    }

    // ---- dense fills: flat16 | flat32 | output_mask -----------------------
    {
        const int gi = B * 384 + t;
        const int T  = 40960 + d_off[5];       // 32768 + 8192 + sumseq
        if (gi < T) {
            if (gi < 32768) {
                int q = gi;
                int m = d_m32[(q >> 10) * 256 + (((q >> 5) & 31) >> 1) * 16 + ((q & 31) >> 1)];
                out[d_off[2] + q] = (float)(1 - m);
            } else if (gi < 40960) {
                int p = gi - 32768;
                out[d_off[3] + p] = (float)d_m32[p];
            } else {
                int j = gi - 40960;            // index into output_mask
                int lo = 0, hi = 32;
                while (hi - lo > 1) {
                    int mid = (lo + hi) >> 1;
                    if (j >= d_cu[mid]) lo = mid; else hi = mid;
                }
                int rel  = j - d_cu[lo];
                int n16b = 1024 - 4 * d_n32b[lo];
                float val = (rel == 0) ? -1.0f : (rel - 1 < n16b ? 1.0f : 2.0f);
                out[d_off[4] + j] = val;
            }
        }
    }
}

// ---------------------------------------------------------------------------
extern "C" void kernel_launch(void* const* d_in, const int* in_sizes, int n_in,
                              void* d_out, int out_size)
{
    const float* img  = (const float*)d_in[0];
    const float* mean = (const float*)d_in[1];
    const float* stdv = (const float*)d_in[2];
    float* out = (float*)d_out;

    entropy_kernel<<<NCOARSE, 256>>>(img, mean, stdv);
    scan_kernel<<<1, 1024>>>(out);
    gather_kernel<<<1024, 384>>>(img, out);
}